// round 1
// baseline (speedup 1.0000x reference)
#include <cuda_runtime.h>
#include <cuda_bf16.h>
#include <cstdint>

#define B_ 4
#define C_ 16
#define H_ 512
#define W_ 512
#define HW_ (H_ * W_)            // 262144
#define NPIX_ (B_ * HW_)         // 1048576
#define EPS_ 1e-10f

// Scratch: packed (priority<<32 | float_bits(Z)) per output pixel. 8 MB.
__device__ unsigned long long g_scratch[NPIX_];
__device__ float g_Kinv[B_][9];
__device__ int g_mask_is_i32;

// ---------------------------------------------------------------------------
// Prep: compute K^-1 per batch (adjugate/det) + detect mask element width.
// ---------------------------------------------------------------------------
__global__ void prep_kernel(const float* __restrict__ K,
                            const void* __restrict__ masks) {
    int t = threadIdx.x;
    if (t < B_) {
        const float* k = K + t * 9;
        float a = k[0], b = k[1], c = k[2];
        float d = k[3], e = k[4], f = k[5];
        float g = k[6], h = k[7], i = k[8];
        float A =  (e * i - f * h);
        float Bc = -(d * i - f * g);
        float Cc =  (d * h - e * g);
        float det = a * A + b * Bc + c * Cc;
        float inv = 1.0f / det;
        float* o = g_Kinv[t];
        o[0] = A * inv;
        o[1] = -(b * i - c * h) * inv;
        o[2] =  (b * f - c * e) * inv;
        o[3] = Bc * inv;
        o[4] =  (a * i - c * g) * inv;
        o[5] = -(a * f - c * d) * inv;
        o[6] = Cc * inv;
        o[7] = -(a * h - b * g) * inv;
        o[8] =  (a * e - b * d) * inv;
    }
    // Mask dtype sniff: one warp scans first 4096 int32 words.
    const unsigned* m32 = (const unsigned*)masks;
    bool bad = false;
    for (int i = t; i < 4096; i += 32)
        bad |= (m32[i] > 1u);
    unsigned any = __ballot_sync(0xffffffffu, bad);
    if (t == 0) g_mask_is_i32 = (any == 0u) ? 1 : 0;
}

// ---------------------------------------------------------------------------
// Init: clear scatter scratch.
// ---------------------------------------------------------------------------
__global__ void init_kernel() {
    int i = blockIdx.x * blockDim.x + threadIdx.x;
    if (i < NPIX_) g_scratch[i] = 0ull;
}

// ---------------------------------------------------------------------------
// Main: unproject -> last-mask transform -> reproject -> priority scatter.
// One thread per pixel; block is batch-uniform (256 | HW).
// ---------------------------------------------------------------------------
__global__ void __launch_bounds__(256, 8)
main_kernel(const float* __restrict__ depth,
            const float* __restrict__ K,
            const float* __restrict__ T,
            const void* __restrict__ masks) {
    __shared__ float sT[C_ * 16];   // 256 floats: all 16 transforms for this batch
    __shared__ float sK[9];
    __shared__ float sKi[9];

    int tid = threadIdx.x;
    int idx = blockIdx.x * 256 + tid;
    int b = idx >> 18;              // / HW_

    sT[tid] = T[b * (C_ * 16) + tid];
    if (tid < 9) {
        sK[tid]  = K[b * 9 + tid];
        sKi[tid] = g_Kinv[b][tid];
    }
    __syncthreads();

    int rem = idx & (HW_ - 1);
    int v = rem >> 9;
    int u = rem & (W_ - 1);

    float d  = depth[idx];
    float uf = (float)u, vf = (float)v;

    // Unproject: pts = (K^-1 @ [u,v,1]) * d
    float x = (sKi[0] * uf + sKi[1] * vf + sKi[2]) * d;
    float y = (sKi[3] * uf + sKi[4] * vf + sKi[5]) * d;
    float z = (sKi[6] * uf + sKi[7] * vf + sKi[8]) * d;

    // Find the LAST channel whose mask is set (later channels win).
    long mbase = (long)b * (C_ * HW_) + rem;
    int c = -1;
    if (g_mask_is_i32) {
        const int* m = (const int*)masks;
        #pragma unroll 1
        for (int cc = C_ - 1; cc >= 0; --cc) {
            if (m[mbase + (long)cc * HW_]) { c = cc; break; }
        }
    } else {
        const unsigned char* m = (const unsigned char*)masks;
        #pragma unroll 1
        for (int cc = C_ - 1; cc >= 0; --cc) {
            if (m[mbase + (long)cc * HW_]) { c = cc; break; }
        }
    }

    if (c >= 0) {
        const float* Tm = &sT[c * 16];
        float tx = Tm[0]  * x + Tm[1]  * y + Tm[2]  * z + Tm[3];
        float ty = Tm[4]  * x + Tm[5]  * y + Tm[6]  * z + Tm[7];
        float tz = Tm[8]  * x + Tm[9]  * y + Tm[10] * z + Tm[11];
        float tw = Tm[12] * x + Tm[13] * y + Tm[14] * z + Tm[15];
        float inv = 1.0f / (tw + EPS_);
        x = tx * inv;
        y = ty * inv;
        z = tz * inv;
    }

    // Reproject: p2h = K @ tp
    float phx = sK[0] * x + sK[1] * y + sK[2] * z;
    float phy = sK[3] * x + sK[4] * y + sK[5] * z;
    float phz = sK[6] * x + sK[7] * y + sK[8] * z;
    float invz = 1.0f / (phz + EPS_);
    float px = phx * invz;
    float py = phy * invz;

    // clip then truncate (matches jnp.clip + astype(int32) for non-neg range;
    // fmaxf/fminf also map NaN -> 0)
    int ui = (int)fminf(fmaxf(px, 0.0f), (float)(W_ - 1));
    int vi = (int)fminf(fmaxf(py, 0.0f), (float)(H_ - 1));

    unsigned long long pkt =
        ((unsigned long long)(unsigned)(rem + 1) << 32) |
        (unsigned long long)__float_as_uint(z);
    atomicMax(&g_scratch[b * HW_ + vi * W_ + ui], pkt);
}

// ---------------------------------------------------------------------------
// Final: resolve scatter (written pixels) else passthrough depth.
// ---------------------------------------------------------------------------
__global__ void final_kernel(const float* __restrict__ depth,
                             float* __restrict__ out) {
    int i = blockIdx.x * blockDim.x + threadIdx.x;
    if (i < NPIX_) {
        unsigned long long s = g_scratch[i];
        out[i] = s ? __uint_as_float((unsigned)s) : depth[i];
    }
}

extern "C" void kernel_launch(void* const* d_in, const int* in_sizes, int n_in,
                              void* d_out, int out_size) {
    const float* depth = (const float*)d_in[0];
    const float* K     = (const float*)d_in[1];
    const float* T     = (const float*)d_in[2];
    const void*  masks = d_in[3];
    float* out = (float*)d_out;

    prep_kernel<<<1, 32>>>(K, masks);
    init_kernel<<<NPIX_ / 512, 512>>>();
    main_kernel<<<NPIX_ / 256, 256>>>(depth, K, T, masks);
    final_kernel<<<NPIX_ / 512, 512>>>(depth, out);
}

// round 2
// speedup vs baseline: 1.4983x; 1.4983x over previous
#include <cuda_runtime.h>
#include <cuda_bf16.h>
#include <cstdint>

#define B_ 4
#define C_ 16
#define H_ 512
#define W_ 512
#define HW_ (H_ * W_)            // 262144
#define NPIX_ (B_ * HW_)         // 1048576
#define EPS_ 1e-10f

// Scratch: packed (priority<<32 | float_bits(Z)) per output pixel. 8 MB.
// Zero-initialized at module load; final_kernel re-zeros after each use so
// every graph replay starts from the same state.
__device__ unsigned long long g_scratch[NPIX_];

// ---------------------------------------------------------------------------
// Main: unproject -> last-mask transform -> reproject -> priority scatter.
// 4 pixels per thread; 1024 px/block -> block is batch-uniform.
// ---------------------------------------------------------------------------
__global__ void __launch_bounds__(256, 8)
main_kernel(const float* __restrict__ depth,
            const float* __restrict__ K,
            const float* __restrict__ T,
            const void* __restrict__ masks) {
    __shared__ float sT[C_ * 16];   // all 16 transforms for this block's batch
    __shared__ float sK[9];
    __shared__ float sKi[9];
    __shared__ int   s_bad;         // mask-dtype sniff: any u32 word > 1 ?

    const int tid  = threadIdx.x;
    const int base = blockIdx.x * 1024;        // first pixel of block
    const int b    = base >> 18;               // / HW_ (constant per block)

    if (tid == 0) {
        s_bad = 0;
        // K^-1 via f32 adjugate (identical formula/precision to R1 kernel)
        const float* k = K + b * 9;
        float a = k[0], bb = k[1], c = k[2];
        float d = k[3], e  = k[4], f = k[5];
        float g = k[6], h  = k[7], i = k[8];
        float A  =  (e * i - f * h);
        float Bc = -(d * i - f * g);
        float Cc =  (d * h - e * g);
        float det = a * A + bb * Bc + c * Cc;
        float inv = 1.0f / det;
        sKi[0] = A * inv;
        sKi[1] = -(bb * i - c * h) * inv;
        sKi[2] =  (bb * f - c * e) * inv;
        sKi[3] = Bc * inv;
        sKi[4] =  (a * i - c * g) * inv;
        sKi[5] = -(a * f - c * d) * inv;
        sKi[6] = Cc * inv;
        sKi[7] = -(a * h - bb * g) * inv;
        sKi[8] =  (a * e - bb * d) * inv;
    }
    sT[tid] = T[b * (C_ * 16) + tid];
    if (tid < 9) sK[tid] = K[b * 9 + tid];
    __syncthreads();

    // Mask dtype sniff: 128 threads read the first 512 bytes as u32.
    // int32 0/1 masks -> every word <= 1. uint8 masks -> words > 1 w.h.p.
    if (tid < 128) {
        unsigned wv = ((const unsigned*)masks)[tid];
        if (wv > 1u) atomicOr(&s_bad, 1);
    }
    __syncthreads();
    const bool mask_is_i32 = (s_bad == 0);

    const int idx  = base + tid * 4;           // first of 4 consecutive pixels
    const int rem  = idx & (HW_ - 1);
    const int v    = rem >> 9;
    const int u    = rem & (W_ - 1);           // u..u+3 same row (4 | 512)

    const float4 d4 = *(const float4*)(depth + idx);
    const float  dd[4] = {d4.x, d4.y, d4.z, d4.w};

    // Find LAST set mask channel per pixel (later channels win).
    const long mbase = (long)b * (C_ * HW_) + rem;
    int cw[4] = {-1, -1, -1, -1};
    if (mask_is_i32) {
        const char* mb = (const char*)masks;
        #pragma unroll 1
        for (int cc = C_ - 1; cc >= 0; --cc) {
            int4 mv = __ldg((const int4*)(mb + 4 * (mbase + (long)cc * HW_)));
            if (cw[0] < 0 && mv.x) cw[0] = cc;
            if (cw[1] < 0 && mv.y) cw[1] = cc;
            if (cw[2] < 0 && mv.z) cw[2] = cc;
            if (cw[3] < 0 && mv.w) cw[3] = cc;
            if ((cw[0] | cw[1] | cw[2] | cw[3]) >= 0) break;
        }
    } else {
        const unsigned char* mb = (const unsigned char*)masks;
        #pragma unroll 1
        for (int cc = C_ - 1; cc >= 0; --cc) {
            unsigned mv = __ldg((const unsigned*)(mb + mbase + (long)cc * HW_));
            if (cw[0] < 0 && (mv & 0x000000ffu)) cw[0] = cc;
            if (cw[1] < 0 && (mv & 0x0000ff00u)) cw[1] = cc;
            if (cw[2] < 0 && (mv & 0x00ff0000u)) cw[2] = cc;
            if (cw[3] < 0 && (mv & 0xff000000u)) cw[3] = cc;
            if ((cw[0] | cw[1] | cw[2] | cw[3]) >= 0) break;
        }
    }

    const float vf = (float)v;
    #pragma unroll
    for (int p = 0; p < 4; ++p) {
        const float uf = (float)(u + p);
        const float d  = dd[p];

        // Unproject: pts = (K^-1 @ [u,v,1]) * d
        float x = (sKi[0] * uf + sKi[1] * vf + sKi[2]) * d;
        float y = (sKi[3] * uf + sKi[4] * vf + sKi[5]) * d;
        float z = (sKi[6] * uf + sKi[7] * vf + sKi[8]) * d;

        const int c = cw[p];
        if (c >= 0) {
            const float* Tm = &sT[c * 16];
            float tx = Tm[0]  * x + Tm[1]  * y + Tm[2]  * z + Tm[3];
            float ty = Tm[4]  * x + Tm[5]  * y + Tm[6]  * z + Tm[7];
            float tz = Tm[8]  * x + Tm[9]  * y + Tm[10] * z + Tm[11];
            float tw = Tm[12] * x + Tm[13] * y + Tm[14] * z + Tm[15];
            float inv = 1.0f / (tw + EPS_);
            x = tx * inv;
            y = ty * inv;
            z = tz * inv;
        }

        // Reproject: p2h = K @ tp
        float phx = sK[0] * x + sK[1] * y + sK[2] * z;
        float phy = sK[3] * x + sK[4] * y + sK[5] * z;
        float phz = sK[6] * x + sK[7] * y + sK[8] * z;
        float invz = 1.0f / (phz + EPS_);
        float px = phx * invz;
        float py = phy * invz;

        // clip then truncate (NaN -> 0 via fmaxf/fminf)
        int ui = (int)fminf(fmaxf(px, 0.0f), (float)(W_ - 1));
        int vi = (int)fminf(fmaxf(py, 0.0f), (float)(H_ - 1));

        unsigned long long pkt =
            ((unsigned long long)(unsigned)(rem + p + 1) << 32) |
            (unsigned long long)__float_as_uint(z);
        atomicMax(&g_scratch[b * HW_ + vi * W_ + ui], pkt);
    }
}

// ---------------------------------------------------------------------------
// Final: resolve scatter (written pixels) else passthrough depth.
// Also re-zeros the scratch for the next invocation / graph replay.
// 4 pixels per thread, fully vectorized.
// ---------------------------------------------------------------------------
__global__ void __launch_bounds__(256)
final_kernel(const float* __restrict__ depth,
             float* __restrict__ out) {
    const int i4 = (blockIdx.x * 256 + threadIdx.x) * 4;

    ulonglong2 s01 = *(ulonglong2*)&g_scratch[i4];
    ulonglong2 s23 = *(ulonglong2*)&g_scratch[i4 + 2];
    const float4 dp = *(const float4*)(depth + i4);

    float4 o;
    o.x = s01.x ? __uint_as_float((unsigned)s01.x) : dp.x;
    o.y = s01.y ? __uint_as_float((unsigned)s01.y) : dp.y;
    o.z = s23.x ? __uint_as_float((unsigned)s23.x) : dp.z;
    o.w = s23.y ? __uint_as_float((unsigned)s23.y) : dp.w;
    *(float4*)(out + i4) = o;

    const ulonglong2 zz = {0ull, 0ull};
    *(ulonglong2*)&g_scratch[i4]     = zz;
    *(ulonglong2*)&g_scratch[i4 + 2] = zz;
}

extern "C" void kernel_launch(void* const* d_in, const int* in_sizes, int n_in,
                              void* d_out, int out_size) {
    const float* depth = (const float*)d_in[0];
    const float* K     = (const float*)d_in[1];
    const float* T     = (const float*)d_in[2];
    const void*  masks = d_in[3];
    float* out = (float*)d_out;

    main_kernel<<<NPIX_ / 1024, 256>>>(depth, K, T, masks);
    final_kernel<<<NPIX_ / 1024, 256>>>(depth, out);
}